// round 6
// baseline (speedup 1.0000x reference)
#include <cuda_runtime.h>
#include <cstdint>

// PeakAligner: L=220, window=[57,87); start=index_max-57 in [0,29]
//   in_bounds <=> start<=28; ss=min(start,28)
//   valid <=> r[ss+57]==max(r[ss..ss+191]) && max(r[ss..ss+56]) < that max && in_bounds
//   downsample: r[ss+3*i], i=0..63

#define L_DIM 220
#define WIN_LEN 30
#define WIN_LO 57
#define MAX_START 28
#define ROWS_PER_TILE 8
#define NBUF 3
#define THREADS 256
#define BLOCKS_PER_SM 8
#define FLOATS_PER_TILE (ROWS_PER_TILE * L_DIM)   // 1760

__device__ __forceinline__ unsigned ford(float f) {
    unsigned u = __float_as_uint(f);
    return u ^ (unsigned)(((int)u >> 31) | 0x80000000);
}
__device__ __forceinline__ float unford(unsigned t) {
    unsigned u = (t & 0x80000000u) ? (t ^ 0x80000000u) : ~t;
    return __uint_as_float(u);
}

__device__ __forceinline__ void prefetch_tile(float* sbuf, const float* __restrict__ in,
                                              int tile, int K) {
    const long long row0 = (long long)tile * ROWS_PER_TILE;
    const int rows_here = min(ROWS_PER_TILE, K - (int)row0);
    const float4* gin = reinterpret_cast<const float4*>(in + row0 * L_DIM);
    const int total4 = rows_here * (L_DIM / 4);
    int i = threadIdx.x;
    if (i < total4) {
        uint32_t sa = (uint32_t)__cvta_generic_to_shared(reinterpret_cast<float4*>(sbuf) + i);
        asm volatile("cp.async.cg.shared.global [%0], [%1], 16;\n" :: "r"(sa), "l"(gin + i));
    }
    i += THREADS;
    if (i < total4) {
        uint32_t sa = (uint32_t)__cvta_generic_to_shared(reinterpret_cast<float4*>(sbuf) + i);
        asm volatile("cp.async.cg.shared.global [%0], [%1], 16;\n" :: "r"(sa), "l"(gin + i));
    }
    asm volatile("cp.async.commit_group;\n");
}

__global__ __launch_bounds__(THREADS)
void peak_aligner_kernel(const float* __restrict__ in,
                         float* __restrict__ out,
                         float* __restrict__ mask_out,
                         int K, int total_tiles, int tiles_per_block) {
    __shared__ float s[NBUF][FLOATS_PER_TILE];    // 21120 B

    const int w    = threadIdx.x >> 5;
    const int lane = threadIdx.x & 31;

    // Contiguous chunk of tiles for this block (persistent, exactly one wave)
    const int tile0 = blockIdx.x * tiles_per_block;
    if (tile0 >= total_tiles) return;
    const int T = min(tiles_per_block, total_tiles - tile0);

    // prime pipeline: prefetch tiles 0 and 1 (distance 2)
    prefetch_tile(s[0], in, tile0, K);
    if (1 < T) prefetch_tile(s[1], in, tile0 + 1, K);

    int buf = 0;
    #pragma unroll 1
    for (int t = 0; t < T; t++) {
        if (t + 2 < T) {
            int pbuf = buf + 2; if (pbuf >= NBUF) pbuf -= NBUF;
            prefetch_tile(s[pbuf], in, tile0 + t + 2, K);
            asm volatile("cp.async.wait_group 2;\n" ::: "memory");
        } else if (t + 1 < T) {
            asm volatile("cp.async.wait_group 1;\n" ::: "memory");
        } else {
            asm volatile("cp.async.wait_group 0;\n" ::: "memory");
        }
        __syncthreads();

        const int tile = tile0 + t;
        const int row0 = tile * ROWS_PER_TILE;
        const int rows_here = min(ROWS_PER_TILE, K - row0);
        if (w < rows_here) {
            const float* r = s[buf] + w * L_DIM;
            const int row = row0 + w;

            // Step 1: first-argmax over window [57,87)
            const unsigned wu = (lane < WIN_LEN) ? ford(r[WIN_LO + lane]) : 0u;
            const unsigned wmax = __reduce_max_sync(0xffffffffu, wu);
            const unsigned wb = __ballot_sync(0xffffffffu, wu == wmax);
            const int start = __ffs(wb) - 1;
            const bool in_bounds = (start <= MAX_START);
            const int ss = min(start, MAX_START);

            // Step 2: valid <=> v57==M(0..191) && P(0..56)<M
            const float* p = r + ss;
            const float x0 = p[lane];
            const float x1 = p[lane + 32];
            const float x2 = p[lane + 64];
            const float x3 = p[lane + 96];
            const float x4 = p[lane + 128];
            const float x5 = p[lane + 160];
            const float Ml = fmaxf(fmaxf(fmaxf(x0, x1), fmaxf(x2, x3)), fmaxf(x4, x5));
            const float Pl = (lane < 25) ? fmaxf(x0, x1) : x0;
            const float M = unford(__reduce_max_sync(0xffffffffu, ford(Ml)));
            const float P = unford(__reduce_max_sync(0xffffffffu, ford(Pl)));
            const float v57 = p[57];
            const bool valid = (v57 == M) && (P < M) && in_bounds;

            // Step 3: downsample + mask (streaming stores)
            const float o0 = valid ? p[3 * lane]      : 0.0f;
            const float o1 = valid ? p[3 * lane + 96] : 0.0f;
            float* orow = out + (size_t)row * 64;
            __stcs(orow + lane,      o0);
            __stcs(orow + lane + 32, o1);
            if (lane == 0)
                __stcs(mask_out + row, valid ? 0.0f : 1.0f);
        }
        __syncthreads();   // everyone done with s[buf] before it is refilled
        buf = (buf + 1 == NBUF) ? 0 : buf + 1;
    }
}

extern "C" void kernel_launch(void* const* d_in, const int* in_sizes, int n_in,
                              void* d_out, int out_size) {
    const float* in = (const float*)d_in[0];
    const int K = in_sizes[0] / L_DIM;
    float* out  = (float*)d_out;
    float* mask = out + (size_t)K * 64;
    const int total_tiles = (K + ROWS_PER_TILE - 1) / ROWS_PER_TILE;

    int sms = 148;
    cudaDeviceGetAttribute(&sms, cudaDevAttrMultiProcessorCount, 0);
    int blocks = sms * BLOCKS_PER_SM;                       // exactly one wave
    const int tiles_per_block = (total_tiles + blocks - 1) / blocks;
    blocks = (total_tiles + tiles_per_block - 1) / tiles_per_block;

    peak_aligner_kernel<<<blocks, THREADS>>>(in, out, mask, K, total_tiles, tiles_per_block);
}

// round 7
// speedup vs baseline: 1.0967x; 1.0967x over previous
#include <cuda_runtime.h>
#include <cstdint>

// PeakAligner: L=220, window=[57,87); start=index_max-57 in [0,29]
//   in_bounds <=> start<=28; ss=min(start,28)
//   valid <=> r[ss+57]==max(r[ss..ss+191]) && max(r[ss..ss+56]) < that max && in_bounds
//   downsample: r[ss+3*i], i=0..63

#define L_DIM 220
#define WIN_LEN 30
#define WIN_LO 57
#define MAX_START 28
#define ROWS_PER_TILE 8
#define TILES_PER_BLOCK 4
#define NBUF 3
#define THREADS 256
#define FLOATS_PER_TILE (ROWS_PER_TILE * L_DIM)   // 1760

__device__ __forceinline__ unsigned ford(float f) {
    unsigned u = __float_as_uint(f);
    return u ^ (unsigned)(((int)u >> 31) | 0x80000000);
}
__device__ __forceinline__ float unford(unsigned t) {
    unsigned u = (t & 0x80000000u) ? (t ^ 0x80000000u) : ~t;
    return __uint_as_float(u);
}

__device__ __forceinline__ void prefetch_tile(float* sbuf, const float* __restrict__ in,
                                              int tile, int K) {
    const long long row0 = (long long)tile * ROWS_PER_TILE;
    const int rows_here = min(ROWS_PER_TILE, K - (int)row0);
    const float4* gin = reinterpret_cast<const float4*>(in + row0 * L_DIM);
    const int total4 = rows_here * (L_DIM / 4);
    int i = threadIdx.x;
    if (i < total4) {
        uint32_t sa = (uint32_t)__cvta_generic_to_shared(reinterpret_cast<float4*>(sbuf) + i);
        asm volatile("cp.async.cg.shared.global [%0], [%1], 16;\n" :: "r"(sa), "l"(gin + i));
    }
    i += THREADS;
    if (i < total4) {
        uint32_t sa = (uint32_t)__cvta_generic_to_shared(reinterpret_cast<float4*>(sbuf) + i);
        asm volatile("cp.async.cg.shared.global [%0], [%1], 16;\n" :: "r"(sa), "l"(gin + i));
    }
    asm volatile("cp.async.commit_group;\n");
}

__global__ __launch_bounds__(THREADS)
void peak_aligner_kernel(const float* __restrict__ in,
                         float* __restrict__ out,
                         float* __restrict__ mask_out,
                         int K, int total_tiles) {
    __shared__ float s[NBUF][FLOATS_PER_TILE];    // 21120 B -> 8 blocks/SM

    const int w    = threadIdx.x >> 5;
    const int lane = threadIdx.x & 31;

    const int tile0 = blockIdx.x * TILES_PER_BLOCK;
    if (tile0 >= total_tiles) return;
    const int T = min(TILES_PER_BLOCK, total_tiles - tile0);

    // prime: prefetch tile 0 (distance-1 pipeline)
    prefetch_tile(s[0], in, tile0, K);

    int buf = 0;
    #pragma unroll 1
    for (int t = 0; t < T; t++) {
        // Prefetch next tile into buf+1 (mod 3). That buffer was last READ at
        // compute(t-2); every warp here passed the barrier of iter t-1, which
        // no warp reaches before finishing compute(t-2) -> safe without a
        // trailing barrier.
        if (t + 1 < T) {
            int pbuf = buf + 1; if (pbuf == NBUF) pbuf = 0;
            prefetch_tile(s[pbuf], in, tile0 + t + 1, K);
            asm volatile("cp.async.wait_group 1;\n" ::: "memory");
        } else {
            asm volatile("cp.async.wait_group 0;\n" ::: "memory");
        }
        __syncthreads();   // single barrier per tile

        const int tile = tile0 + t;
        const int row0 = tile * ROWS_PER_TILE;
        const int rows_here = min(ROWS_PER_TILE, K - row0);
        if (w < rows_here) {
            const float* r = s[buf] + w * L_DIM;
            const int row = row0 + w;

            // Step 1: first-argmax over window [57,87)
            const unsigned wu = (lane < WIN_LEN) ? ford(r[WIN_LO + lane]) : 0u;
            const unsigned wmax = __reduce_max_sync(0xffffffffu, wu);
            const unsigned wb = __ballot_sync(0xffffffffu, wu == wmax);
            const int start = __ffs(wb) - 1;
            const bool in_bounds = (start <= MAX_START);
            const int ss = min(start, MAX_START);

            // Step 2: valid <=> v57==M(0..191) && P(0..56)<M
            const float* p = r + ss;
            const float x0 = p[lane];
            const float x1 = p[lane + 32];
            const float x2 = p[lane + 64];
            const float x3 = p[lane + 96];
            const float x4 = p[lane + 128];
            const float x5 = p[lane + 160];
            const float Ml = fmaxf(fmaxf(fmaxf(x0, x1), fmaxf(x2, x3)), fmaxf(x4, x5));
            const float Pl = (lane < 25) ? fmaxf(x0, x1) : x0;
            const float M = unford(__reduce_max_sync(0xffffffffu, ford(Ml)));
            const float P = unford(__reduce_max_sync(0xffffffffu, ford(Pl)));
            const float v57 = p[57];
            const bool valid = (v57 == M) && (P < M) && in_bounds;

            // Step 3: downsample + mask (streaming stores)
            const float o0 = valid ? p[3 * lane]      : 0.0f;
            const float o1 = valid ? p[3 * lane + 96] : 0.0f;
            float* orow = out + (size_t)row * 64;
            __stcs(orow + lane,      o0);
            __stcs(orow + lane + 32, o1);
            if (lane == 0)
                __stcs(mask_out + row, valid ? 0.0f : 1.0f);
        }
        buf = (buf + 1 == NBUF) ? 0 : buf + 1;
    }
}

extern "C" void kernel_launch(void* const* d_in, const int* in_sizes, int n_in,
                              void* d_out, int out_size) {
    const float* in = (const float*)d_in[0];
    const int K = in_sizes[0] / L_DIM;
    float* out  = (float*)d_out;
    float* mask = out + (size_t)K * 64;
    const int total_tiles = (K + ROWS_PER_TILE - 1) / ROWS_PER_TILE;
    const int blocks = (total_tiles + TILES_PER_BLOCK - 1) / TILES_PER_BLOCK;
    peak_aligner_kernel<<<blocks, THREADS>>>(in, out, mask, K, total_tiles);
}